// round 7
// baseline (speedup 1.0000x reference)
#include <cuda_runtime.h>
#include <cstdint>

#define M_Q   4096
#define N_B   65536
#define D_DIM 128
#define KNN   9
#define MTILE 128
#define NTILE 128
#define NSPLIT 9                      // one-wave grid: 32*9 = 288 CTAs
#define NT_TOTAL (N_B / NTILE)        // 512 n-tiles
#define THREADS 256
#define PART_STRIDE 12
#define NLISTS NSPLIT
#define TILE_BYTES (128 * D_DIM)      // 16KB per packed int8 tile
#define QSCALE 23.090909f             // 127 / 5.5
#define QS2    (QSCALE * QSCALE)

// ---------------------------------------------------------------------------
// Device-global scratch
// ---------------------------------------------------------------------------
__device__ __align__(16) int   g_part[NLISTS * M_Q * PART_STRIDE];
__device__ __align__(16) int   g_K[N_B];          // (bsq + 1024) / s^2, rounded
__device__ __align__(16) int8_t g_bt[(size_t)N_B * D_DIM];   // packed pre-swizzled
__device__ __align__(16) int8_t g_qt[(size_t)M_Q * D_DIM];

// ---------------------------------------------------------------------------
// SMEM: A 16KB, B 2x16KB, K 2x512B, mbarriers
// ---------------------------------------------------------------------------
#define OFF_A    0
#define OFF_B    16384
#define OFF_K    (16384 + 2 * 16384)     // 49152
#define OFF_MBAR (OFF_K + 2 * 512)       // 50176
#define SMEM_SZ  (OFF_MBAR + 64)

// ---------------------------------------------------------------------------
// PTX helpers (sm_80/sm_90 baseline only)
// ---------------------------------------------------------------------------
__device__ __forceinline__ uint32_t smem_u32(const void* p) {
    uint32_t a;
    asm("{ .reg .u64 t; cvta.to.shared.u64 t, %1; cvt.u32.u64 %0, t; }" : "=r"(a) : "l"(p));
    return a;
}
__device__ __forceinline__ void ldsm4(uint32_t* r, uint32_t addr) {
    asm volatile("ldmatrix.sync.aligned.m8n8.x4.shared.b16 {%0,%1,%2,%3}, [%4];"
                 : "=r"(r[0]), "=r"(r[1]), "=r"(r[2]), "=r"(r[3]) : "r"(addr));
}
__device__ __forceinline__ void mma_s8(int* c, const uint32_t* a, const uint32_t* b) {
    asm volatile(
        "mma.sync.aligned.m16n8k32.row.col.s32.s8.s8.s32 "
        "{%0,%1,%2,%3}, {%4,%5,%6,%7}, {%8,%9}, {%0,%1,%2,%3};"
        : "+r"(c[0]), "+r"(c[1]), "+r"(c[2]), "+r"(c[3])
        : "r"(a[0]), "r"(a[1]), "r"(a[2]), "r"(a[3]), "r"(b[0]), "r"(b[1]));
}
#define MBAR_INIT(a, c) \
    asm volatile("mbarrier.init.shared.b64 [%0], %1;" :: "r"(a), "r"(c) : "memory")
#define MBAR_EXPECT_TX(a, tx) \
    asm volatile("mbarrier.arrive.expect_tx.shared.b64 _, [%0], %1;" :: "r"(a), "r"(tx) : "memory")
#define MBAR_WAIT(a, ph) do {                                                   \
    asm volatile(                                                               \
        "{\n\t.reg .pred P1;\n\t"                                               \
        "WAIT_LOOP_%=:\n\t"                                                     \
        "mbarrier.try_wait.parity.acquire.cta.shared::cta.b64 P1, [%0], %1, 0x989680;\n\t" \
        "@P1 bra.uni WAIT_DONE_%=;\n\t"                                         \
        "bra.uni WAIT_LOOP_%=;\n\t"                                             \
        "WAIT_DONE_%=:\n\t}"                                                    \
        :: "r"(a), "r"(ph) : "memory");                                         \
} while (0)
__device__ __forceinline__ void bulk_g2s(uint32_t dst, const void* src,
                                         uint32_t bytes, uint32_t mbar) {
    asm volatile(
        "cp.async.bulk.shared::cluster.global.mbarrier::complete_tx::bytes "
        "[%0], [%1], %2, [%3];"
        :: "r"(dst), "l"(src), "r"(bytes), "r"(mbar) : "memory");
}

// ---------------------------------------------------------------------------
// Pre-pass: fp32 -> int8 packed pre-swizzled tiles (+ selection key base K).
// Thread i: vec = i>>3, 16B chunk c = i&7 (16 elements).
// ---------------------------------------------------------------------------
__global__ void pack_q_kernel(const float4* __restrict__ src,
                              uint4* __restrict__ dst,
                              int* __restrict__ Kout, int nthreads) {
    int i = blockIdx.x * blockDim.x + threadIdx.x;
    if (i >= nthreads) return;
    int vec = i >> 3, c = i & 7;
    int tile = vec >> 7, r = vec & 127;

    float f[16];
    float nrm = 0.0f;
    uint32_t w[4];
#pragma unroll
    for (int v = 0; v < 4; v++) {
        float4 x = src[(size_t)vec * 32 + c * 4 + v];
        f[4 * v + 0] = x.x; f[4 * v + 1] = x.y; f[4 * v + 2] = x.z; f[4 * v + 3] = x.w;
    }
#pragma unroll
    for (int e = 0; e < 16; e++) nrm += f[e] * f[e];
#pragma unroll
    for (int v = 0; v < 4; v++) {
        int b0 = __float2int_rn(fminf(fmaxf(f[4 * v + 0] * QSCALE, -127.f), 127.f));
        int b1 = __float2int_rn(fminf(fmaxf(f[4 * v + 1] * QSCALE, -127.f), 127.f));
        int b2 = __float2int_rn(fminf(fmaxf(f[4 * v + 2] * QSCALE, -127.f), 127.f));
        int b3 = __float2int_rn(fminf(fmaxf(f[4 * v + 3] * QSCALE, -127.f), 127.f));
        w[v] = (b0 & 0xFF) | ((b1 & 0xFF) << 8) | ((b2 & 0xFF) << 16) | (b3 << 24);
    }
    uint32_t off = (uint32_t)tile * 16384 + r * 128 + (((uint32_t)(c ^ (r & 7))) << 4);
    uint4 o; o.x = w[0]; o.y = w[1]; o.z = w[2]; o.w = w[3];
    dst[off >> 4] = o;

    if (Kout) {
#pragma unroll
        for (int offv = 4; offv; offv >>= 1) nrm += __shfl_xor_sync(0xffffffffu, nrm, offv);
        if (c == 0) Kout[vec] = (int)rintf((nrm + 1024.0f) * QS2);
    }
}

// ---------------------------------------------------------------------------
// Streaming int top-9
// ---------------------------------------------------------------------------
__device__ __forceinline__ void top9i(int k, int (&h)[KNN], int& thr) {
    if (k < thr) {
        bool done = false;
#pragma unroll
        for (int i = 0; i < KNN; i++)
            if (!done && h[i] == thr) { h[i] = k; done = true; }
        int m = h[0];
#pragma unroll
        for (int i = 1; i < KNN; i++) m = max(m, h[i]);
        thr = m;
    }
}

// ---------------------------------------------------------------------------
// Main kernel: int8 m16n8k32 GEMM + integer key top-9 (with packed index)
// grid = (32, 9)
// ---------------------------------------------------------------------------
__global__ void __launch_bounds__(THREADS, 2) knn_main_kernel() {
    extern __shared__ char smem[];
    const uint32_t sm = smem_u32(smem);
    const int tid  = threadIdx.x;
    const int wid  = tid >> 5;
    const int lane = tid & 31;
    const int g    = lane >> 2;
    const int tig  = lane & 3;
    const int qtile = blockIdx.x;
    const int qbase = qtile * MTILE;
    const int b0  = (NT_TOTAL * blockIdx.y) / NSPLIT;
    const int cnt = (NT_TOTAL * (blockIdx.y + 1)) / NSPLIT - b0;
    const int IMAX = 0x7fffffff;

    if (tid == 0) { MBAR_INIT(sm + OFF_MBAR, 1); MBAR_INIT(sm + OFF_MBAR + 8, 1); }
    __syncthreads();

    if (tid == 0) {
        MBAR_EXPECT_TX(sm + OFF_MBAR, 16384u + 16384u + 512u);
        bulk_g2s(sm + OFF_A, g_qt + (size_t)qtile * TILE_BYTES, 16384u, sm + OFF_MBAR);
        bulk_g2s(sm + OFF_B, g_bt + (size_t)b0 * TILE_BYTES, 16384u, sm + OFF_MBAR);
        bulk_g2s(sm + OFF_K, g_K + b0 * NTILE, 512u, sm + OFF_MBAR);
        MBAR_EXPECT_TX(sm + OFF_MBAR + 8, 16384u + 512u);
        bulk_g2s(sm + OFF_B + 16384, g_bt + (size_t)(b0 + 1) * TILE_BYTES, 16384u,
                 sm + OFF_MBAR + 8);
        bulk_g2s(sm + OFF_K + 512, g_K + (b0 + 1) * NTILE, 512u, sm + OFF_MBAR + 8);
    }

    MBAR_WAIT(sm + OFF_MBAR, 0);

    // preload A fragments: 4 k-steps (k32 each)
    // lane -> row (lane&7) + ((lane>>3)&1)*8 ; chunk 2s + (lane>>4)
    uint32_t aF[4][4];
    {
        const int m0 = wid * 16;
        const int rA = (lane & 7) + (((lane >> 3) & 1) << 3);
        const uint32_t arow = sm + OFF_A + (m0 + rA) * 128;
        const int hiA = lane >> 4;
#pragma unroll
        for (int s = 0; s < 4; s++)
            ldsm4(aF[s], arow + ((((uint32_t)(2 * s + hiA)) ^ (rA & 7)) << 4));
    }

    int heap0[KNN], heap1[KNN];
    int thr0 = IMAX, thr1 = IMAX;
#pragma unroll
    for (int i = 0; i < KNN; i++) { heap0[i] = IMAX; heap1[i] = IMAX; }

    // B ldmatrix lane mapping: row (lane&7)+((lane>>4)<<3), chunk parity (lane>>3)&1
    const int rB   = (lane & 7) + ((lane >> 4) << 3);
    const int shiB = (lane >> 3) & 1;

#pragma unroll 1
    for (int t = 0; t < cnt; t++) {
        const int buf = t & 1;

        if (t > 0) MBAR_WAIT(sm + OFF_MBAR + buf * 8, (t >> 1) & 1);

        const uint32_t Bb = sm + OFF_B + buf * 16384;
        const int* Ks = (const int*)(smem + OFF_K + buf * 512);

#pragma unroll
        for (int half = 0; half < 2; half++) {
            int acc[8][4];
#pragma unroll
            for (int f = 0; f < 8; f++)
#pragma unroll
                for (int x = 0; x < 4; x++) acc[f][x] = 0;

#pragma unroll
            for (int s = 0; s < 4; s++) {
                const uint32_t segoff = (((uint32_t)(2 * s + shiB)) ^ (rB & 7)) << 4;
#pragma unroll
                for (int p = 0; p < 4; p++) {   // pair of n8-blocks (16 rows)
                    uint32_t b[4];
                    ldsm4(b, Bb + (half * 64 + p * 16 + rB) * 128 + segoff);
                    mma_s8(acc[2 * p],     aF[s], b);
                    mma_s8(acc[2 * p + 1], aF[s], b + 2);
                }
            }

            // epilogue: key = ((K_col - 2*dot) & ~7) << 10 | local_j
#pragma unroll
            for (int f = 0; f < 8; f++) {
                const int col = half * 64 + f * 8 + 2 * tig;
                const int jl  = t * 128 + col;
                const int K0 = Ks[col], K1 = Ks[col + 1];
                int k0 = (((K0 - 2 * acc[f][0]) & ~7) << 10) | jl;
                int k1 = (((K1 - 2 * acc[f][1]) & ~7) << 10) | (jl + 1);
                int k2 = (((K0 - 2 * acc[f][2]) & ~7) << 10) | jl;
                int k3 = (((K1 - 2 * acc[f][3]) & ~7) << 10) | (jl + 1);
                top9i(k0, heap0, thr0);
                top9i(k1, heap0, thr0);
                top9i(k2, heap1, thr1);
                top9i(k3, heap1, thr1);
            }
        }

        __syncthreads();
        if (t + 2 < cnt && tid == 0) {
            MBAR_EXPECT_TX(sm + OFF_MBAR + buf * 8, 16384u + 512u);
            bulk_g2s(sm + OFF_B + buf * 16384,
                     g_bt + (size_t)(b0 + t + 2) * TILE_BYTES, 16384u,
                     sm + OFF_MBAR + buf * 8);
            bulk_g2s(sm + OFF_K + buf * 512, g_K + (b0 + t + 2) * NTILE, 512u,
                     sm + OFF_MBAR + buf * 8);
        }
    }

    // quad merge across tig lanes -> tig 0
    const unsigned FULL = 0xffffffffu;
#pragma unroll
    for (int src = 1; src < 4; src++) {
#pragma unroll
        for (int i = 0; i < KNN; i++) {
            int v0 = __shfl_sync(FULL, heap0[i], (lane & ~3) + src);
            int v1 = __shfl_sync(FULL, heap1[i], (lane & ~3) + src);
            if (tig == 0) { top9i(v0, heap0, thr0); top9i(v1, heap1, thr1); }
        }
    }

    if (tig == 0) {
        const int row0 = qbase + wid * 16 + g;
        size_t p0 = ((size_t)blockIdx.y * M_Q + row0) * PART_STRIDE;
        size_t p1 = ((size_t)blockIdx.y * M_Q + row0 + 8) * PART_STRIDE;
#pragma unroll
        for (int r = 0; r < KNN; r++) {
            g_part[p0 + r] = heap0[r];
            g_part[p1 + r] = heap1[r];
        }
    }
}

// ---------------------------------------------------------------------------
// Finalize: exact fp32 rescore of the 81 candidates per query.
// One warp per query; lane owns 4 dims.
// ---------------------------------------------------------------------------
__global__ void knn_finalize_kernel(const float4* __restrict__ q,
                                    const float4* __restrict__ b,
                                    float* __restrict__ out) {
    const int wid  = threadIdx.x >> 5;
    const int lane = threadIdx.x & 31;
    const int qi   = blockIdx.x * 8 + wid;
    if (qi >= M_Q) return;
    const float INF = __int_as_float(0x7f800000);

    float4 qv = q[(size_t)qi * 32 + lane];

    float heap[KNN], thr = INF;
#pragma unroll
    for (int i = 0; i < KNN; i++) heap[i] = INF;

#pragma unroll 1
    for (int l = 0; l < NLISTS; l++) {
        const int base = ((NT_TOTAL * l) / NSPLIT) * NTILE;
        const int* p = &g_part[((size_t)l * M_Q + qi) * PART_STRIDE];
#pragma unroll 1
        for (int r = 0; r < KNN; r++) {
            int j = base + (p[r] & 8191);
            j = min(j, N_B - 1);
            float4 bv = b[(size_t)j * 32 + lane];
            float dx = qv.x - bv.x, dy = qv.y - bv.y;
            float dz = qv.z - bv.z, dw = qv.w - bv.w;
            float d = dx * dx + dy * dy + dz * dz + dw * dw;
#pragma unroll
            for (int off = 16; off; off >>= 1)
                d += __shfl_xor_sync(0xffffffffu, d, off);
            if (lane == 0) {
                if (d < thr) {
                    bool done = false;
#pragma unroll
                    for (int i = 0; i < KNN; i++)
                        if (!done && heap[i] == thr) { heap[i] = d; done = true; }
                    float m = heap[0];
#pragma unroll
                    for (int i = 1; i < KNN; i++) m = fmaxf(m, heap[i]);
                    thr = m;
                }
            }
        }
    }

    if (lane == 0) {
        float sum = 0.0f;
#pragma unroll
        for (int i = 0; i < KNN; i++) sum += sqrtf(fmaxf(heap[i], 0.0f));
        out[qi] = sum * (1.0f / KNN);
    }
}

// ---------------------------------------------------------------------------
extern "C" void kernel_launch(void* const* d_in, const int* in_sizes, int n_in,
                              void* d_out, int out_size)
{
    const float* q = (const float*)d_in[0];   // features    [4096,128]
    const float* b = (const float*)d_in[1];   // memory_bank [65536,128]
    if (n_in >= 2 && in_sizes[0] > in_sizes[1]) {
        const float* tmp = q; q = b; b = tmp;
    }
    float* out = (float*)d_out;

    static uint4* p_bt = nullptr;
    static uint4* p_qt = nullptr;
    static int*   p_K  = nullptr;
    if (!p_bt) {
        cudaGetSymbolAddress((void**)&p_bt, g_bt);
        cudaGetSymbolAddress((void**)&p_qt, g_qt);
        cudaGetSymbolAddress((void**)&p_K,  g_K);
    }

    cudaFuncSetAttribute(knn_main_kernel,
                         cudaFuncAttributeMaxDynamicSharedMemorySize, SMEM_SZ);

    pack_q_kernel<<<N_B * 8 / 256, 256>>>((const float4*)b, p_bt, p_K, N_B * 8);
    pack_q_kernel<<<M_Q * 8 / 256, 256>>>((const float4*)q, p_qt, nullptr, M_Q * 8);

    dim3 grid(M_Q / MTILE, NSPLIT);
    knn_main_kernel<<<grid, THREADS, SMEM_SZ>>>();

    knn_finalize_kernel<<<M_Q / 8, 256>>>((const float4*)q, (const float4*)b, out);
}